// round 2
// baseline (speedup 1.0000x reference)
#include <cuda_runtime.h>
#include <math.h>

#define B 96
#define N 512
#define M 512
#define D 32

// Cost matrix scratch: row-major per batch. 96*512*512*4B = 100.7 MB.
__device__ float g_cost[(size_t)B * N * M];

// ---------------------------------------------------------------------------
// Kernel 1: pairwise L2 cost matrices.
// grid (96, 4), block 512. CTA (b, chunk) computes rows [chunk*128, +128) of
// batch b's cost matrix. Thread j owns column j: keeps seq2[b][j][:] in
// registers, reads seq1 rows from a 16KB smem stage (broadcast LDS.128).
// ---------------------------------------------------------------------------
__global__ void __launch_bounds__(512) cost_kernel(const float* __restrict__ seq1,
                                                   const float* __restrict__ seq2)
{
    const int b = blockIdx.x;
    const int chunk = blockIdx.y;
    const int j = threadIdx.x;

    const float* s1 = seq1 + (size_t)b * N * D;
    const float* s2 = seq2 + (size_t)b * M * D;

    // own seq2 row -> registers (8 x float4 = 32 floats)
    float4 s2r[8];
    const float4* s2v = reinterpret_cast<const float4*>(s2 + j * D);
#pragma unroll
    for (int q = 0; q < 8; ++q) s2r[q] = s2v[q];

    float sq2 = 0.f;
#pragma unroll
    for (int q = 0; q < 8; ++q) {
        sq2 = fmaf(s2r[q].x, s2r[q].x, sq2);
        sq2 = fmaf(s2r[q].y, s2r[q].y, sq2);
        sq2 = fmaf(s2r[q].z, s2r[q].z, sq2);
        sq2 = fmaf(s2r[q].w, s2r[q].w, sq2);
    }

    __shared__ float sh_s1[128 * D];   // 16 KB
    __shared__ float sh_sq1[128];

    const int r0 = chunk * 128;

    // cooperative stage of 128 seq1 rows
    {
        const float4* src = reinterpret_cast<const float4*>(s1 + r0 * D);
        float4* dst = reinterpret_cast<float4*>(sh_s1);
        for (int idx = j; idx < 128 * D / 4; idx += 512) dst[idx] = src[idx];
    }
    __syncthreads();

    if (j < 128) {
        float acc = 0.f;
#pragma unroll
        for (int k = 0; k < D; ++k) {
            float a = sh_s1[j * D + k];
            acc = fmaf(a, a, acc);
        }
        sh_sq1[j] = acc;
    }
    __syncthreads();

    float* outp = g_cost + (size_t)b * N * M + (size_t)r0 * M + j;

    for (int i = 0; i < 128; ++i) {
        const float4* a = reinterpret_cast<const float4*>(sh_s1 + i * D);
        float d0 = 0.f, d1 = 0.f, d2a = 0.f, d3 = 0.f;
#pragma unroll
        for (int q = 0; q < 8; ++q) {
            float4 av = a[q];
            d0 = fmaf(av.x, s2r[q].x, d0);
            d1 = fmaf(av.y, s2r[q].y, d1);
            d2a = fmaf(av.z, s2r[q].z, d2a);
            d3 = fmaf(av.w, s2r[q].w, d3);
        }
        float dot = (d0 + d1) + (d2a + d3);
        float dd = sh_sq1[i] + sq2 - 2.f * dot;
        outp[(size_t)i * M] = sqrtf(fmaxf(dd, 1e-12f));
    }
}

// ---------------------------------------------------------------------------
// Kernel 2: DTW wavefront. One warp per batch. Thread t owns columns
// [16t, 16t+16). At step s, thread t processes row r = s - t. Inter-thread
// dependency is a single shfl_up per step (neighbor's last-column value).
// Cost rows are prefetched 2 steps ahead (register double+1 buffering).
// ---------------------------------------------------------------------------
__global__ void __launch_bounds__(32) dtw_kernel(float* __restrict__ out)
{
    const int b = blockIdx.x;
    const int t = threadIdx.x;
    const float INF = INFINITY;

    const float* base = g_cost + (size_t)b * N * M + t * 16;

    float vprev[16];
#pragma unroll
    for (int k = 0; k < 16; ++k) vprev[k] = INF;

    float diag0 = (t == 0) ? 0.f : INF;   // D[r-1][j0-1]
    float lastv = INF;                     // my last computed column value

    // prefetch rows 0 and 1 (every thread's first row is row 0)
    float4 cur[4], nxt[4];
    {
        const float4* p0 = reinterpret_cast<const float4*>(base + 0 * M);
        const float4* p1 = reinterpret_cast<const float4*>(base + 1 * M);
#pragma unroll
        for (int q = 0; q < 4; ++q) { cur[q] = p0[q]; nxt[q] = p1[q]; }
    }

    const int STEPS = N + 31;   // 543

    for (int s = 0; s < STEPS; ++s) {
        // neighbor's value from previous step = D[r][j0-1] (my "left" entry)
        float left0 = __shfl_up_sync(0xffffffffu, lastv, 1);
        if (t == 0) left0 = INF;

        const int r = s - t;
        if (r >= 0 && r < N) {
            // issue prefetch for row r+2 first (hides DRAM latency)
            float4 nx[4] = {make_float4(0,0,0,0), make_float4(0,0,0,0),
                            make_float4(0,0,0,0), make_float4(0,0,0,0)};
            const int rp = r + 2;
            if (rp < N) {
                const float4* p = reinterpret_cast<const float4*>(base + (size_t)rp * M);
#pragma unroll
                for (int q = 0; q < 4; ++q) nx[q] = p[q];
            }

            float c[16];
#pragma unroll
            for (int q = 0; q < 4; ++q) {
                c[4*q + 0] = cur[q].x;
                c[4*q + 1] = cur[q].y;
                c[4*q + 2] = cur[q].z;
                c[4*q + 3] = cur[q].w;
            }

            float left = left0;
            float dprev = diag0;   // D[r-1][j-1] for k=0
#pragma unroll
            for (int k = 0; k < 16; ++k) {
                float up = vprev[k];             // D[r-1][j]
                float m = fminf(up, dprev);      // min(up, diag)
                float v = c[k] + fminf(left, m);
                dprev = up;
                vprev[k] = v;
                left = v;
            }
            lastv = left;       // vprev[15] of row r
            diag0 = left0;      // becomes D[r][j0-1] for the next row

#pragma unroll
            for (int q = 0; q < 4; ++q) { cur[q] = nxt[q]; nxt[q] = nx[q]; }
        }
    }

    if (t == 31) out[b] = lastv;   // D[N-1][M-1]
}

// ---------------------------------------------------------------------------
extern "C" void kernel_launch(void* const* d_in, const int* in_sizes, int n_in,
                              void* d_out, int out_size)
{
    const float* seq1 = (const float*)d_in[0];
    const float* seq2 = (const float*)d_in[1];
    float* out = (float*)d_out;

    dim3 g1(B, 4);
    cost_kernel<<<g1, 512>>>(seq1, seq2);
    dtw_kernel<<<B, 32>>>(out);
}

// round 4
// speedup vs baseline: 2.8334x; 2.8334x over previous
#include <cuda_runtime.h>
#include <cstdint>
#include <math.h>

#define B 96
#define N 512
#define M 512
#define D 32

// Cost matrix scratch: row-major per batch. 96*512*512*4B = 100.7 MB.
__device__ float g_cost[(size_t)B * N * M];

// ---------------------------------------------------------------------------
// Kernel 1: pairwise L2 cost matrices.  (unchanged — ~88us)
// ---------------------------------------------------------------------------
__global__ void __launch_bounds__(512) cost_kernel(const float* __restrict__ seq1,
                                                   const float* __restrict__ seq2)
{
    const int b = blockIdx.x;
    const int chunk = blockIdx.y;
    const int j = threadIdx.x;

    const float* s1 = seq1 + (size_t)b * N * D;
    const float* s2 = seq2 + (size_t)b * M * D;

    float4 s2r[8];
    const float4* s2v = reinterpret_cast<const float4*>(s2 + j * D);
#pragma unroll
    for (int q = 0; q < 8; ++q) s2r[q] = s2v[q];

    float sq2 = 0.f;
#pragma unroll
    for (int q = 0; q < 8; ++q) {
        sq2 = fmaf(s2r[q].x, s2r[q].x, sq2);
        sq2 = fmaf(s2r[q].y, s2r[q].y, sq2);
        sq2 = fmaf(s2r[q].z, s2r[q].z, sq2);
        sq2 = fmaf(s2r[q].w, s2r[q].w, sq2);
    }

    __shared__ float sh_s1[128 * D];
    __shared__ float sh_sq1[128];

    const int r0 = chunk * 128;

    {
        const float4* src = reinterpret_cast<const float4*>(s1 + r0 * D);
        float4* dst = reinterpret_cast<float4*>(sh_s1);
        for (int idx = j; idx < 128 * D / 4; idx += 512) dst[idx] = src[idx];
    }
    __syncthreads();

    if (j < 128) {
        float acc = 0.f;
#pragma unroll
        for (int k = 0; k < D; ++k) {
            float a = sh_s1[j * D + k];
            acc = fmaf(a, a, acc);
        }
        sh_sq1[j] = acc;
    }
    __syncthreads();

    float* outp = g_cost + (size_t)b * N * M + (size_t)r0 * M + j;

    for (int i = 0; i < 128; ++i) {
        const float4* a = reinterpret_cast<const float4*>(sh_s1 + i * D);
        float d0 = 0.f, d1 = 0.f, d2a = 0.f, d3 = 0.f;
#pragma unroll
        for (int q = 0; q < 8; ++q) {
            float4 av = a[q];
            d0 = fmaf(av.x, s2r[q].x, d0);
            d1 = fmaf(av.y, s2r[q].y, d1);
            d2a = fmaf(av.z, s2r[q].z, d2a);
            d3 = fmaf(av.w, s2r[q].w, d3);
        }
        float dot = (d0 + d1) + (d2a + d3);
        float dd = sh_sq1[i] + sq2 - 2.f * dot;
        outp[(size_t)i * M] = sqrtf(fmaxf(dd, 1e-12f));
    }
}

// ---------------------------------------------------------------------------
// Kernel 2: DTW wavefront with cp.async smem ring (prefetch distance 6).
// One warp per batch. Thread t owns columns [16t,16t+16); at step s it
// processes row r = s - t. Cross-thread dep = one shfl_up per step.
// Cost rows stream GMEM->SMEM via LDGSTS, so no register scoreboard wait
// sits on the recurrence chain. Each thread touches only its own 80B
// region per ring slot -> zero barriers.
// ---------------------------------------------------------------------------
#define RING 8
#define PF 6
#define SLOT_F 640            // 32 threads * 20 floats (16 data + 4 pad)
#define TSTRIDE_F 20          // per-thread floats in a slot (80B: conflict-free)

__device__ __forceinline__ void cp_async16(unsigned dst, const float* src) {
    asm volatile("cp.async.cg.shared.global [%0], [%1], 16;\n"
                 :: "r"(dst), "l"(src) : "memory");
}

__global__ void __launch_bounds__(32) dtw_kernel(float* __restrict__ out)
{
    const int b = blockIdx.x;
    const int t = threadIdx.x;
    const float INF = INFINITY;

    const float* base = g_cost + (size_t)b * N * M + t * 16;

    __shared__ float ring[RING * SLOT_F];   // 20 KB
    const unsigned my_s =
        (unsigned)__cvta_generic_to_shared(ring) + (unsigned)(t * TSTRIDE_F * 4);

    // prologue: stage rows 0..PF-1, one commit group per row
#pragma unroll
    for (int p = 0; p < PF; ++p) {
        const float* src = base + (size_t)p * M;
        unsigned dst = my_s + (unsigned)((p % RING) * SLOT_F * 4);
#pragma unroll
        for (int q = 0; q < 4; ++q) cp_async16(dst + q * 16, src + q * 4);
        asm volatile("cp.async.commit_group;\n" ::: "memory");
    }

    float vprev[16];
#pragma unroll
    for (int k = 0; k < 16; ++k) vprev[k] = INF;

    float diag0 = (t == 0) ? 0.f : INF;   // D[r-1][j0-1]
    float lastv = INF;

    const int STEPS = N + 31;   // 543

    for (int s = 0; s < STEPS; ++s) {
        float left0 = __shfl_up_sync(0xffffffffu, lastv, 1);
        if (t == 0) left0 = INF;

        const int r = s - t;

        // prefetch row r+PF into the ring (predicated per thread)
        if (r >= 0 && r + PF < N) {
            const float* src = base + (size_t)(r + PF) * M;
            unsigned dst = my_s + (unsigned)(((r + PF) % RING) * SLOT_F * 4);
#pragma unroll
            for (int q = 0; q < 4; ++q) cp_async16(dst + q * 16, src + q * 4);
        }
        asm volatile("cp.async.commit_group;\n" ::: "memory");
        // after this, all groups up through the one staged for row r are done
        asm volatile("cp.async.wait_group 6;\n" ::: "memory");

        if (r >= 0 && r < N) {
            const float4* cp = reinterpret_cast<const float4*>(
                &ring[(r % RING) * SLOT_F + t * TSTRIDE_F]);
            float4 c0 = cp[0], c1 = cp[1], c2 = cp[2], c3 = cp[3];
            float c[16] = { c0.x, c0.y, c0.z, c0.w,
                            c1.x, c1.y, c1.z, c1.w,
                            c2.x, c2.y, c2.z, c2.w,
                            c3.x, c3.y, c3.z, c3.w };

            // off-chain: m[k] = min(up, diag) — all parallel
            float m[16];
            m[0] = fminf(vprev[0], diag0);
#pragma unroll
            for (int k = 1; k < 16; ++k) m[k] = fminf(vprev[k], vprev[k - 1]);

            // serial chain: v = c + min(left, m); 2 ops/column
            float left = left0;
#pragma unroll
            for (int k = 0; k < 16; ++k) {
                float v = c[k] + fminf(left, m[k]);
                vprev[k] = v;
                left = v;
            }
            lastv = left;
            diag0 = left0;
        }
    }

    if (t == 31) out[b] = lastv;   // D[N-1][M-1]
}

// ---------------------------------------------------------------------------
extern "C" void kernel_launch(void* const* d_in, const int* in_sizes, int n_in,
                              void* d_out, int out_size)
{
    const float* seq1 = (const float*)d_in[0];
    const float* seq2 = (const float*)d_in[1];
    float* out = (float*)d_out;

    dim3 g1(B, 4);
    cost_kernel<<<g1, 512>>>(seq1, seq2);
    dtw_kernel<<<B, 32>>>(out);
}

// round 6
// speedup vs baseline: 3.0519x; 1.0771x over previous
#include <cuda_runtime.h>
#include <cstdint>
#include <math.h>

#define B 96
#define N 512
#define M 512
#define D 32

// Cost matrix scratch: row-major per batch. 96*512*512*4B = 100.7 MB.
__device__ float g_cost[(size_t)B * N * M];

// ---------------------------------------------------------------------------
// f32x2 packed helpers (Blackwell FFMA2 — only reachable via PTX)
// ---------------------------------------------------------------------------
__device__ __forceinline__ unsigned long long pack2f(float x, float y) {
    unsigned long long r;
    asm("mov.b64 %0, {%1, %2};" : "=l"(r) : "f"(x), "f"(y));
    return r;
}
__device__ __forceinline__ void ffma2(unsigned long long& d,
                                      unsigned long long a, unsigned long long b) {
    asm("fma.rn.f32x2 %0, %1, %2, %0;" : "+l"(d) : "l"(a), "l"(b));
}
__device__ __forceinline__ void unpack2f(unsigned long long v, float& x, float& y) {
    asm("mov.b64 {%0, %1}, %2;" : "=f"(x), "=f"(y) : "l"(v));
}
__device__ __forceinline__ void lds_v2u64(unsigned saddr,
                                          unsigned long long& a, unsigned long long& b) {
    asm("ld.shared.v2.u64 {%0, %1}, [%2];" : "=l"(a), "=l"(b) : "r"(saddr));
}
__device__ __forceinline__ float fast_sqrt(float x) {
    float r;
    asm("sqrt.approx.f32 %0, %1;" : "=f"(r) : "f"(x));
    return r;
}

// ---------------------------------------------------------------------------
// Kernel 1: pairwise L2 cost matrices, FFMA2 path, 1 row per iteration.
// grid (96,4), block 512. Thread j owns column j (seq2 row j in registers,
// pre-packed as 16 u64 = ALL 32 floats). seq1 rows staged in smem,
// read as 8 x v2.u64 (full 128B row).
// ---------------------------------------------------------------------------
__global__ void __launch_bounds__(512) cost_kernel(const float* __restrict__ seq1,
                                                   const float* __restrict__ seq2)
{
    const int b = blockIdx.x;
    const int chunk = blockIdx.y;
    const int j = threadIdx.x;

    const float* s1 = seq1 + (size_t)b * N * D;
    const float* s2 = seq2 + (size_t)b * M * D;

    // own seq2 row -> registers, packed into 16 u64 pairs (covers all 32 floats)
    unsigned long long s2p[16];
    float sq2 = 0.f;
    {
        const float4* s2v = reinterpret_cast<const float4*>(s2 + j * D);
#pragma unroll
        for (int q = 0; q < 8; ++q) {
            float4 v = s2v[q];
            s2p[2 * q]     = pack2f(v.x, v.y);
            s2p[2 * q + 1] = pack2f(v.z, v.w);
            sq2 = fmaf(v.x, v.x, sq2);
            sq2 = fmaf(v.y, v.y, sq2);
            sq2 = fmaf(v.z, v.z, sq2);
            sq2 = fmaf(v.w, v.w, sq2);
        }
    }

    __shared__ float sh_s1[128 * D];   // 16 KB
    __shared__ float sh_sq1[128];

    const int r0 = chunk * 128;

    {
        const float4* src = reinterpret_cast<const float4*>(s1 + r0 * D);
        float4* dst = reinterpret_cast<float4*>(sh_s1);
        for (int idx = j; idx < 128 * D / 4; idx += 512) dst[idx] = src[idx];
    }
    __syncthreads();

    if (j < 128) {
        float acc = 0.f;
#pragma unroll
        for (int k = 0; k < D; ++k) {
            float a = sh_s1[j * D + k];
            acc = fmaf(a, a, acc);
        }
        sh_sq1[j] = acc;
    }
    __syncthreads();

    const unsigned sbase = (unsigned)__cvta_generic_to_shared(sh_s1);
    float* outp = g_cost + (size_t)b * N * M + (size_t)r0 * M + j;

    for (int i = 0; i < 128; ++i) {
        const unsigned row = sbase + (unsigned)(i * D * 4);   // 128B per row

        unsigned long long a[16];
#pragma unroll
        for (int q = 0; q < 8; ++q)            // 8 x 16B = full 128B row
            lds_v2u64(row + q * 16, a[2 * q], a[2 * q + 1]);

        unsigned long long acc0 = 0ull, acc1 = 0ull, acc2 = 0ull, acc3 = 0ull;
#pragma unroll
        for (int u = 0; u < 16; u += 4) {
            ffma2(acc0, a[u],     s2p[u]);
            ffma2(acc1, a[u + 1], s2p[u + 1]);
            ffma2(acc2, a[u + 2], s2p[u + 2]);
            ffma2(acc3, a[u + 3], s2p[u + 3]);
        }

        float e0, e1, e2, e3, e4, e5, e6, e7;
        unpack2f(acc0, e0, e1);
        unpack2f(acc1, e2, e3);
        unpack2f(acc2, e4, e5);
        unpack2f(acc3, e6, e7);
        float dot = ((e0 + e1) + (e2 + e3)) + ((e4 + e5) + (e6 + e7));

        float dd = sh_sq1[i] + sq2 - 2.f * dot;
        outp[(size_t)i * M] = fast_sqrt(fmaxf(dd, 1e-12f));
    }
}

// ---------------------------------------------------------------------------
// Kernel 2: DTW wavefront, cp.async ring (PF=7) + min-plus prefix restructure.
// v[k] = P[k] + min(left0, Wmin[k]) with P = prefix-sum(c),
// w[j] = m[j] - P[j-1], Wmin = prefix-min(w), m[j] = min(up, diag).
// Everything except one FMNMX+FADD happens before left0 arrives via shfl,
// so the 16-column serial chain is off the inter-step critical path.
// ---------------------------------------------------------------------------
#define RING 8
#define PF 7
#define SLOT_F 640            // 32 threads * 20 floats (16 data + 4 pad)
#define TSTRIDE_F 20

__device__ __forceinline__ void cp_async16(unsigned dst, const float* src) {
    asm volatile("cp.async.cg.shared.global [%0], [%1], 16;\n"
                 :: "r"(dst), "l"(src) : "memory");
}

__global__ void __launch_bounds__(32) dtw_kernel(float* __restrict__ out)
{
    const int b = blockIdx.x;
    const int t = threadIdx.x;
    const float INF = INFINITY;

    const float* base = g_cost + (size_t)b * N * M + t * 16;

    __shared__ float ring[RING * SLOT_F];   // 20 KB
    const unsigned my_s =
        (unsigned)__cvta_generic_to_shared(ring) + (unsigned)(t * TSTRIDE_F * 4);

    // prologue: stage rows 0..PF-1
#pragma unroll
    for (int p = 0; p < PF; ++p) {
        const float* src = base + (size_t)p * M;
        unsigned dst = my_s + (unsigned)((p % RING) * SLOT_F * 4);
#pragma unroll
        for (int q = 0; q < 4; ++q) cp_async16(dst + q * 16, src + q * 4);
        asm volatile("cp.async.commit_group;\n" ::: "memory");
    }

    float vprev[16];
#pragma unroll
    for (int k = 0; k < 16; ++k) vprev[k] = INF;

    float diag0 = (t == 0) ? 0.f : INF;   // D[r-1][j0-1]
    float lastv = INF;

    const int STEPS = N + 31;   // 543

    for (int s = 0; s < STEPS; ++s) {
        float left0 = __shfl_up_sync(0xffffffffu, lastv, 1);
        if (t == 0) left0 = INF;

        const int r = s - t;

        if (r >= 0 && r + PF < N) {
            const float* src = base + (size_t)(r + PF) * M;
            unsigned dst = my_s + (unsigned)(((r + PF) % RING) * SLOT_F * 4);
#pragma unroll
            for (int q = 0; q < 4; ++q) cp_async16(dst + q * 16, src + q * 4);
        }
        asm volatile("cp.async.commit_group;\n" ::: "memory");
        asm volatile("cp.async.wait_group %0;\n" :: "n"(PF) : "memory");

        if (r >= 0 && r < N) {
            const float4* cp = reinterpret_cast<const float4*>(
                &ring[(r % RING) * SLOT_F + t * TSTRIDE_F]);
            float4 c0 = cp[0], c1 = cp[1], c2 = cp[2], c3 = cp[3];
            float c[16] = { c0.x, c0.y, c0.z, c0.w,
                            c1.x, c1.y, c1.z, c1.w,
                            c2.x, c2.y, c2.z, c2.w,
                            c3.x, c3.y, c3.z, c3.w };

            // P[k] = prefix sum of c (serial, off the inter-step chain)
            float P[16];
            P[0] = c[0];
#pragma unroll
            for (int k = 1; k < 16; ++k) P[k] = P[k - 1] + c[k];

            // m[k] = min(up, diag) — parallel;  w[k] = m[k] - P[k-1]
            float w[16];
            {
                float m0 = fminf(vprev[0], diag0);
                w[0] = m0;                       // P[-1] = 0
#pragma unroll
                for (int k = 1; k < 16; ++k) {
                    float mk = fminf(vprev[k], vprev[k - 1]);
                    w[k] = mk - P[k - 1];
                }
            }

            // Wmin[k] = prefix-min of w (serial, off-chain)
#pragma unroll
            for (int k = 1; k < 16; ++k) w[k] = fminf(w[k], w[k - 1]);

            // v[k] = P[k] + min(left0, Wmin[k]) — left0 only enters here
#pragma unroll
            for (int k = 0; k < 16; ++k)
                vprev[k] = P[k] + fminf(left0, w[k]);

            lastv = vprev[15];
            diag0 = left0;
        }
    }

    if (t == 31) out[b] = lastv;   // D[N-1][M-1]
}

// ---------------------------------------------------------------------------
extern "C" void kernel_launch(void* const* d_in, const int* in_sizes, int n_in,
                              void* d_out, int out_size)
{
    const float* seq1 = (const float*)d_in[0];
    const float* seq2 = (const float*)d_in[1];
    float* out = (float*)d_out;

    dim3 g1(B, 4);
    cost_kernel<<<g1, 512>>>(seq1, seq2);
    dtw_kernel<<<B, 32>>>(out);
}